// round 3
// baseline (speedup 1.0000x reference)
#include <cuda_runtime.h>

// SignalDualBackground: out[b,c,s,t] = (1 - spikes[b,c,s,t]) * stat[b,c,t]
//   x[b,c,t]  = mean_s spikes[b,c,s,t]            (S=64)
//   stat[.,t] = beta*stat[.,t-1] + (1-beta)*x[.,t], stat[.,-1]=0  (T=1024)
//
// R3: persistent software-pipelined kernel. 1 CTA/SM (smem pad), 1024 thr.
// Each CTA round-robins tiles (tile = one (b,c), 256KB). Pipeline:
//   phase1(tile j+1) loads overlap scan(tile j) [warps 8-31] and
//   phase3(tile j) stores [warp group 0 interleaves its own prefetch].
// Scan sync among the 8 part-0 warps uses named barrier 1 (256 threads) so
// the other 24 warps never wait on it. Phase-3 re-read hits L2 (2 tiles in
// flight per SM * ~150 SMs ~= 76MB < 126MB L2). __ldcs/__stcs keep output
// traffic from evicting live spike lines.

#define T_DIM 1024
#define S_DIM 64
#define THREADS 1024
#define T4 (T_DIM / 4)            // 256 float4 per row
#define S_PER_PART 16             // 64 synapse rows / 4 parts
#define TILE_F4 (S_DIM * T4)      // 16384 float4 per tile
#define PAD_SMEM (100 * 1024)     // force 1 CTA/SM

__global__ __launch_bounds__(THREADS, 1)
void sdb_kernel(const float4* __restrict__ sp,
                const float* __restrict__ beta_p,
                float4* __restrict__ out, int n_tiles) {
    extern __shared__ float smem_pad[];   // occupancy limiter
    (void)smem_pad;
    __shared__ float4 red[THREADS];       // 16 KB synapse partials
    __shared__ float4 statS[T4];          // 4 KB broadcast stat
    __shared__ float Ms[8], As[8];

    const int tid  = threadIdx.x;
    const int col  = tid & (T4 - 1);      // 0..255 time chunk
    const int part = tid >> 8;            // 0..3 synapse partition
    const int lane = tid & 31;
    const int wid  = tid >> 5;            // 0..31 (part0 -> 0..7)
    const int s0r  = part * S_PER_PART;

    const float beta = beta_p[0];
    const float omb  = 1.0f - beta;
    const float inv  = 1.0f / (float)S_DIM;
    const int stride = gridDim.x;

    int tile = blockIdx.x;
    if (tile >= n_tiles) return;

    // ---- prologue: phase 1 of first tile ----
    float4 sum = make_float4(0.f, 0.f, 0.f, 0.f);
    {
        const float4* spb = sp + (size_t)tile * TILE_F4;
        #pragma unroll
        for (int k = 0; k < S_PER_PART; ++k) {
            float4 v = spb[(s0r + k) * T4 + col];
            sum.x += v.x; sum.y += v.y; sum.z += v.z; sum.w += v.w;
        }
    }

    while (tile < n_tiles) {
        const int next = tile + stride;
        const bool has_next = (next < n_tiles);
        const float4* spb_cur = sp  + (size_t)tile * TILE_F4;
        float4*       ob_cur  = out + (size_t)tile * TILE_F4;
        const float4* spb_nxt = sp  + (size_t)next * TILE_F4;

        red[tid] = sum;
        __syncthreads();                          // barrier A

        float4 nsum = make_float4(0.f, 0.f, 0.f, 0.f);
        if (part == 0) {
            // ---- combine partials + parallel linear-recurrence scan ----
            float4 a4 = red[col];
            float4 b4 = red[col + 256];
            float4 c4 = red[col + 512];
            float4 d4 = red[col + 768];
            const float x0 = (a4.x + b4.x + c4.x + d4.x) * inv;
            const float x1 = (a4.y + b4.y + c4.y + d4.y) * inv;
            const float x2 = (a4.z + b4.z + c4.z + d4.z) * inv;
            const float x3 = (a4.w + b4.w + c4.w + d4.w) * inv;

            // per-thread composite over 4 steps: state' = m*state + a
            float a = omb * x0;
            a = beta * a + omb * x1;
            a = beta * a + omb * x2;
            a = beta * a + omb * x3;
            float m = beta * beta;
            m = m * m;                            // beta^4

            #pragma unroll
            for (int d = 1; d < 32; d <<= 1) {
                float ap = __shfl_up_sync(0xffffffffu, a, d);
                float mp = __shfl_up_sync(0xffffffffu, m, d);
                if (lane >= d) { a += m * ap; m *= mp; }
            }
            if (lane == 31) { Ms[wid] = m; As[wid] = a; }
            // sync only the 8 part-0 warps (256 threads), named barrier 1
            asm volatile("bar.sync 1, 256;" ::: "memory");

            // serial compose of warp aggregates [0..wid-1]
            float pref = 0.0f;
            #pragma unroll
            for (int w = 0; w < 8; ++w) {
                if (w == wid) break;
                pref = Ms[w] * pref + As[w];
            }
            const float a_full = a + m * pref;
            const float a_prev = __shfl_up_sync(0xffffffffu, a_full, 1);
            const float a_excl = (lane > 0) ? a_prev : pref;

            float st = a_excl;
            st = beta * st + omb * x0; const float r0 = st;
            st = beta * st + omb * x1; const float r1 = st;
            st = beta * st + omb * x2; const float r2 = st;
            st = beta * st + omb * x3; const float r3 = st;
            statS[col] = make_float4(r0, r1, r2, r3);
        } else if (has_next) {
            // ---- warps 8..31: phase 1 of NEXT tile (hides the scan) ----
            #pragma unroll
            for (int k = 0; k < S_PER_PART; ++k) {
                float4 v = spb_nxt[(s0r + k) * T4 + col];
                nsum.x += v.x; nsum.y += v.y; nsum.z += v.z; nsum.w += v.w;
            }
        }
        __syncthreads();                          // barrier B

        // ---- phase 3: out = (1-spike)*stat ; re-read hits L2 ----
        const float4 st4 = statS[col];
        if (part == 0 && has_next) {
            // part 0 interleaves its next-tile prefetch with phase 3
            #pragma unroll
            for (int k = 0; k < S_PER_PART; ++k) {
                const size_t idx = (size_t)(s0r + k) * T4 + col;
                float4 nv = spb_nxt[idx];
                nsum.x += nv.x; nsum.y += nv.y; nsum.z += nv.z; nsum.w += nv.w;
                float4 v = __ldcs(&spb_cur[idx]);
                float4 o;
                o.x = (1.0f - v.x) * st4.x;
                o.y = (1.0f - v.y) * st4.y;
                o.z = (1.0f - v.z) * st4.z;
                o.w = (1.0f - v.w) * st4.w;
                __stcs(&ob_cur[idx], o);
            }
        } else {
            #pragma unroll
            for (int k = 0; k < S_PER_PART; ++k) {
                const size_t idx = (size_t)(s0r + k) * T4 + col;
                float4 v = __ldcs(&spb_cur[idx]);
                float4 o;
                o.x = (1.0f - v.x) * st4.x;
                o.y = (1.0f - v.y) * st4.y;
                o.z = (1.0f - v.z) * st4.z;
                o.w = (1.0f - v.w) * st4.w;
                __stcs(&ob_cur[idx], o);
            }
        }
        sum = nsum;
        tile = next;
    }
}

extern "C" void kernel_launch(void* const* d_in, const int* in_sizes, int n_in,
                              void* d_out, int out_size) {
    const float* spikes = (const float*)d_in[0];
    const float* beta   = (const float*)d_in[1];
    float* out          = (float*)d_out;

    const int nbc = in_sizes[0] / (S_DIM * T_DIM);  // 2048 tiles

    int dev = 0, nsm = 148;
    cudaGetDevice(&dev);
    cudaDeviceGetAttribute(&nsm, cudaDevAttrMultiProcessorCount, dev);
    int grid = nsm < nbc ? nsm : nbc;

    cudaFuncSetAttribute(sdb_kernel,
                         cudaFuncAttributeMaxDynamicSharedMemorySize, PAD_SMEM);
    sdb_kernel<<<grid, THREADS, PAD_SMEM>>>(
        (const float4*)spikes, beta, (float4*)out, nbc);
}

// round 4
// speedup vs baseline: 1.0682x; 1.0682x over previous
#include <cuda_runtime.h>

// SignalDualBackground: out[b,c,s,t] = (1 - spikes[b,c,s,t]) * stat[b,c,t]
//   x[b,c,t]  = mean_s spikes[b,c,s,t]            (S=64)
//   stat[.,t] = beta*stat[.,t-1] + (1-beta)*x[.,t], stat[.,-1]=0  (T=1024)
//
// R4: back to R2's non-persistent one-CTA-per-tile structure (ideal 1.02GB
// traffic), but 512 threads/CTA at 2 CTAs/SM so the two CTAs' barrier/scan
// bubbles interleave and DRAM stays busy. L2 footprint: 2 tiles/SM * 148SM
// = 76MB of read lines < 126MB L2 (stores use __stcs, phase-3 reads __ldcs,
// so only phase-1 read lines占 L2) -> phase-3 re-read still hits L2.

#define T_DIM 1024
#define S_DIM 64
#define THREADS 512
#define T4 (T_DIM / 4)            // 256 float4 per row
#define S_PER_PART 32             // 64 synapse rows / 2 parts
#define TILE_F4 (S_DIM * T4)      // 16384 float4 per tile
#define PAD_SMEM (100 * 1024)     // static ~12KB + 100KB -> 112KB/CTA -> 2 CTAs/SM

__global__ __launch_bounds__(THREADS, 2)
void sdb_kernel(const float4* __restrict__ sp,
                const float* __restrict__ beta_p,
                float4* __restrict__ out) {
    extern __shared__ float smem_pad[];   // occupancy limiter (2 CTAs/SM)
    (void)smem_pad;
    __shared__ float4 red[THREADS];       // 8 KB synapse partials
    __shared__ float4 statS[T4];          // 4 KB broadcast stat
    __shared__ float Ms[8], As[8];

    const int tid  = threadIdx.x;
    const int col  = tid & (T4 - 1);      // 0..255 time chunk
    const int part = tid >> 8;            // 0..1 synapse partition
    const int lane = tid & 31;
    const int wid  = tid >> 5;            // 0..15 (part0 -> 0..7)
    const int s0r  = part * S_PER_PART;

    const size_t base = (size_t)blockIdx.x * TILE_F4;
    const float4* spb = sp + base;
    float4* ob = out + base;

    const float beta = beta_p[0];
    const float omb  = 1.0f - beta;

    // ---------- Phase 1: partial sums over 32 synapse rows ----------
    float4 sum = make_float4(0.f, 0.f, 0.f, 0.f);
    #pragma unroll
    for (int k = 0; k < S_PER_PART; ++k) {
        float4 v = spb[(s0r + k) * T4 + col];
        sum.x += v.x; sum.y += v.y; sum.z += v.z; sum.w += v.w;
    }
    red[tid] = sum;
    __syncthreads();                      // barrier A

    // ---------- Phase 2: finish mean + parallel scan (warps 0..7) ----------
    if (part == 0) {
        float4 a4 = red[col];
        float4 b4 = red[col + 256];
        const float inv = 1.0f / (float)S_DIM;
        const float x0 = (a4.x + b4.x) * inv;
        const float x1 = (a4.y + b4.y) * inv;
        const float x2 = (a4.z + b4.z) * inv;
        const float x3 = (a4.w + b4.w) * inv;

        // per-thread composite over 4 time steps: state' = m*state + a
        float a = omb * x0;
        a = beta * a + omb * x1;
        a = beta * a + omb * x2;
        a = beta * a + omb * x3;
        float m = beta * beta;
        m = m * m;                        // beta^4

        // warp inclusive scan of (m, a)
        #pragma unroll
        for (int d = 1; d < 32; d <<= 1) {
            float ap = __shfl_up_sync(0xffffffffu, a, d);
            float mp = __shfl_up_sync(0xffffffffu, m, d);
            if (lane >= d) { a += m * ap; m *= mp; }
        }
        if (lane == 31) { Ms[wid] = m; As[wid] = a; }
        // sync only the 8 part-0 warps (256 threads): named barrier 1
        asm volatile("bar.sync 1, 256;" ::: "memory");

        // serial compose of warp aggregates [0..wid-1] (tiny)
        float pref = 0.0f;
        #pragma unroll
        for (int w = 0; w < 8; ++w) {
            if (w == wid) break;
            pref = Ms[w] * pref + As[w];
        }
        const float a_full = a + m * pref;
        const float a_prev = __shfl_up_sync(0xffffffffu, a_full, 1);
        const float a_excl = (lane > 0) ? a_prev : pref;

        float st = a_excl;
        st = beta * st + omb * x0; const float r0 = st;
        st = beta * st + omb * x1; const float r1 = st;
        st = beta * st + omb * x2; const float r2 = st;
        st = beta * st + omb * x3; const float r3 = st;
        statS[col] = make_float4(r0, r1, r2, r3);
    }
    __syncthreads();                      // barrier B

    // ---------- Phase 3: out = (1-spike)*stat ; re-read hits L2 ----------
    const float4 st4 = statS[col];
    #pragma unroll
    for (int k = 0; k < S_PER_PART; ++k) {
        const size_t idx = (size_t)(s0r + k) * T4 + col;
        float4 v = __ldcs(&spb[idx]);     // last use: evict-first
        float4 o;
        o.x = (1.0f - v.x) * st4.x;
        o.y = (1.0f - v.y) * st4.y;
        o.z = (1.0f - v.z) * st4.z;
        o.w = (1.0f - v.w) * st4.w;
        __stcs(&ob[idx], o);              // streaming store
    }
}

extern "C" void kernel_launch(void* const* d_in, const int* in_sizes, int n_in,
                              void* d_out, int out_size) {
    const float* spikes = (const float*)d_in[0];
    const float* beta   = (const float*)d_in[1];
    float* out          = (float*)d_out;

    const int nbc = in_sizes[0] / (S_DIM * T_DIM);  // 16*128 = 2048 tiles

    cudaFuncSetAttribute(sdb_kernel,
                         cudaFuncAttributeMaxDynamicSharedMemorySize, PAD_SMEM);
    sdb_kernel<<<nbc, THREADS, PAD_SMEM>>>(
        (const float4*)spikes, beta, (float4*)out);
}

// round 5
// speedup vs baseline: 1.2537x; 1.1737x over previous
#include <cuda_runtime.h>

// SignalDualBackground: out[b,c,s,t] = (1 - spikes[b,c,s,t]) * stat[b,c,t]
//   x[b,c,t]  = mean_s spikes[b,c,s,t]            (S=64)
//   stat[.,t] = beta*stat[.,t-1] + (1-beta)*x[.,t], stat[.,-1]=0  (T=1024)
//
// R5: R2 structure (one CTA per (b,c) tile, ideal 1.02GB traffic) but at
// FULL occupancy: 1024 threads/CTA, 2 CTAs/SM (capped by the 2048-thread
// limit, no smem pad needed), 64 warps/SM. The co-resident CTA fills the
// scan/barrier bubbles with its own DRAM loads/stores. 32 regs/thread
// (launch_bounds(1024,2)) -> moderate unroll to avoid spills.
// L2 footprint 2 tiles/SM * 148 = 76MB < 126MB, so the phase-3 re-read
// still hits L2 (validated by R4's 1.08GB traffic at the same footprint).

#define T_DIM 1024
#define S_DIM 64
#define THREADS 1024
#define T4 (T_DIM / 4)            // 256 float4 per row
#define S_PER_PART 16             // 64 synapse rows / 4 parts
#define TILE_F4 (S_DIM * T4)      // 16384 float4 per tile

__global__ __launch_bounds__(THREADS, 2)
void sdb_kernel(const float4* __restrict__ sp,
                const float* __restrict__ beta_p,
                float4* __restrict__ out) {
    __shared__ float4 red[THREADS];       // 16 KB synapse partials
    __shared__ float4 statS[T4];          // 4 KB broadcast stat
    __shared__ float Ms[8], As[8];

    const int tid  = threadIdx.x;
    const int col  = tid & (T4 - 1);      // 0..255 time chunk
    const int part = tid >> 8;            // 0..3 synapse partition
    const int lane = tid & 31;
    const int wid  = tid >> 5;            // 0..31 (part0 -> 0..7)
    const int s0r  = part * S_PER_PART;

    const size_t base = (size_t)blockIdx.x * TILE_F4;
    const float4* spb = sp + base;
    float4* ob = out + base;

    const float beta = beta_p[0];
    const float omb  = 1.0f - beta;

    // ---------- Phase 1: partial sums over 16 synapse rows ----------
    // Two accumulators shorten the FADD dependency chain; unroll 4 keeps
    // 4 float4 loads in flight within the 32-reg budget.
    float4 acc0 = make_float4(0.f, 0.f, 0.f, 0.f);
    float4 acc1 = make_float4(0.f, 0.f, 0.f, 0.f);
    const float4* p = spb + (size_t)s0r * T4 + col;
    #pragma unroll 4
    for (int k = 0; k < S_PER_PART; k += 2) {
        float4 v0 = p[(size_t)k * T4];
        float4 v1 = p[(size_t)(k + 1) * T4];
        acc0.x += v0.x; acc0.y += v0.y; acc0.z += v0.z; acc0.w += v0.w;
        acc1.x += v1.x; acc1.y += v1.y; acc1.z += v1.z; acc1.w += v1.w;
    }
    acc0.x += acc1.x; acc0.y += acc1.y; acc0.z += acc1.z; acc0.w += acc1.w;
    red[tid] = acc0;
    __syncthreads();                      // barrier A

    // ---------- Phase 2: finish mean + parallel scan (warps 0..7) ----------
    if (part == 0) {
        float4 a4 = red[col];
        float4 b4 = red[col + 256];
        float4 c4 = red[col + 512];
        float4 d4 = red[col + 768];
        const float inv = 1.0f / (float)S_DIM;
        const float x0 = (a4.x + b4.x + c4.x + d4.x) * inv;
        const float x1 = (a4.y + b4.y + c4.y + d4.y) * inv;
        const float x2 = (a4.z + b4.z + c4.z + d4.z) * inv;
        const float x3 = (a4.w + b4.w + c4.w + d4.w) * inv;

        // per-thread composite over 4 time steps: state' = m*state + a
        float a = omb * x0;
        a = beta * a + omb * x1;
        a = beta * a + omb * x2;
        a = beta * a + omb * x3;
        float m = beta * beta;
        m = m * m;                        // beta^4

        // warp inclusive scan of (m, a)
        #pragma unroll
        for (int d = 1; d < 32; d <<= 1) {
            float ap = __shfl_up_sync(0xffffffffu, a, d);
            float mp = __shfl_up_sync(0xffffffffu, m, d);
            if (lane >= d) { a += m * ap; m *= mp; }
        }
        if (lane == 31) { Ms[wid] = m; As[wid] = a; }
        // sync only the 8 part-0 warps (256 threads): named barrier 1
        asm volatile("bar.sync 1, 256;" ::: "memory");

        // serial compose of warp aggregates [0..wid-1] (tiny)
        float pref = 0.0f;
        #pragma unroll
        for (int w = 0; w < 8; ++w) {
            if (w == wid) break;
            pref = Ms[w] * pref + As[w];
        }
        const float a_full = a + m * pref;
        const float a_prev = __shfl_up_sync(0xffffffffu, a_full, 1);
        const float a_excl = (lane > 0) ? a_prev : pref;

        float st = a_excl;
        st = beta * st + omb * x0; const float r0 = st;
        st = beta * st + omb * x1; const float r1 = st;
        st = beta * st + omb * x2; const float r2 = st;
        st = beta * st + omb * x3; const float r3 = st;
        statS[col] = make_float4(r0, r1, r2, r3);
    }
    __syncthreads();                      // barrier B

    // ---------- Phase 3: out = (1-spike)*stat ; re-read hits L2 ----------
    const float4 st4 = statS[col];
    const float4* pr = spb + (size_t)s0r * T4 + col;
    float4* pw = ob + (size_t)s0r * T4 + col;
    #pragma unroll 4
    for (int k = 0; k < S_PER_PART; ++k) {
        float4 v = __ldcs(&pr[(size_t)k * T4]);   // last use: evict-first
        float4 o;
        o.x = (1.0f - v.x) * st4.x;
        o.y = (1.0f - v.y) * st4.y;
        o.z = (1.0f - v.z) * st4.z;
        o.w = (1.0f - v.w) * st4.w;
        __stcs(&pw[(size_t)k * T4], o);           // streaming store
    }
}

extern "C" void kernel_launch(void* const* d_in, const int* in_sizes, int n_in,
                              void* d_out, int out_size) {
    const float* spikes = (const float*)d_in[0];
    const float* beta   = (const float*)d_in[1];
    float* out          = (float*)d_out;

    const int nbc = in_sizes[0] / (S_DIM * T_DIM);  // 16*128 = 2048 tiles

    sdb_kernel<<<nbc, THREADS>>>(
        (const float4*)spikes, beta, (float4*)out);
}

// round 6
// speedup vs baseline: 1.3647x; 1.0886x over previous
#include <cuda_runtime.h>
#include <cstdint>

// SignalDualBackground: out[b,c,s,t] = (1 - spikes[b,c,s,t]) * stat[b,c,t]
//   x[b,c,t]  = mean_s spikes[b,c,s,t]            (S=64)
//   stat[.,t] = beta*stat[.,t-1] + (1-beta)*x[.,t], stat[.,-1]=0  (T=1024)
//
// R6: cluster-of-2 cooperative tiles. Two 1024-thread CTAs (one cluster)
// share one 256KB (b,c) tile: rank r owns synapse rows [r*32, r*32+32).
// This keeps R5's 64 warps/SM (DRAM busy ~79%) while halving the L2
// between-touch footprint to 148 tiles * 256KB / ... = 38MB, so the phase-3
// re-read hits L2 (~ideal 1.02GB DRAM traffic).
// Cross-CTA: rank1 DSMEM-writes its per-col partial sums to rank0; rank0
// scans and DSMEM-writes stat back; two barrier.cluster syncs order it.

#define T_DIM 1024
#define S_DIM 64
#define THREADS 1024
#define T4 (T_DIM / 4)              // 256 float4 per row
#define ROWS_PER_CTA 32
#define ROWS_PER_THREAD 8           // 32 rows / 4 parts
#define TILE_F4 (S_DIM * T4)        // 16384 float4 per tile

__device__ __forceinline__ uint32_t smem_u32(const void* p) {
    uint32_t a;
    asm("{ .reg .u64 t; cvta.to.shared.u64 t, %1; cvt.u32.u64 %0, t; }"
        : "=r"(a) : "l"(p));
    return a;
}

__global__ __launch_bounds__(THREADS, 2) __cluster_dims__(2, 1, 1)
void sdb_kernel(const float4* __restrict__ sp,
                const float* __restrict__ beta_p,
                float4* __restrict__ out) {
    __shared__ float4 red[THREADS];   // 16KB: per-thread partials
    __shared__ float4 statS[T4];      // 4KB: broadcast stat
    __shared__ float4 peerSum[T4];    // 4KB: rank1 -> rank0 partials
    __shared__ float Ms[8], As[8];

    const int tid  = threadIdx.x;
    const int col  = tid & (T4 - 1);  // 0..255 time chunk
    const int part = tid >> 8;        // 0..3
    const int lane = tid & 31;
    const int wid  = tid >> 5;        // part0 -> 0..7

    const int rank = (int)(blockIdx.x & 1);      // ctarank within cluster
    const size_t base = (size_t)(blockIdx.x >> 1) * TILE_F4;
    const int srow0 = rank * ROWS_PER_CTA + part * ROWS_PER_THREAD;

    const float beta = beta_p[0];
    const float omb  = 1.0f - beta;

    // ---------- Phase 1: partial sums over this CTA's 8 rows/thread ----------
    const float4* p = sp + base + (size_t)srow0 * T4 + col;
    float4 acc0 = make_float4(0.f, 0.f, 0.f, 0.f);
    float4 acc1 = make_float4(0.f, 0.f, 0.f, 0.f);
    #pragma unroll
    for (int k = 0; k < ROWS_PER_THREAD; k += 2) {
        float4 v0 = p[(size_t)k * T4];
        float4 v1 = p[(size_t)(k + 1) * T4];
        acc0.x += v0.x; acc0.y += v0.y; acc0.z += v0.z; acc0.w += v0.w;
        acc1.x += v1.x; acc1.y += v1.y; acc1.z += v1.z; acc1.w += v1.w;
    }
    acc0.x += acc1.x; acc0.y += acc1.y; acc0.z += acc1.z; acc0.w += acc1.w;
    red[tid] = acc0;
    __syncthreads();

    // per-col sum over this CTA's 32 rows (part 0 only), kept in regs
    float4 csum;
    if (part == 0) {
        float4 a4 = red[col];
        float4 b4 = red[col + 256];
        float4 c4 = red[col + 512];
        float4 d4 = red[col + 768];
        csum.x = a4.x + b4.x + c4.x + d4.x;
        csum.y = a4.y + b4.y + c4.y + d4.y;
        csum.z = a4.z + b4.z + c4.z + d4.z;
        csum.w = a4.w + b4.w + c4.w + d4.w;
        if (rank == 1) {
            // DSMEM write into rank0's peerSum[col]
            uint32_t la = smem_u32(&peerSum[col]);
            uint32_t ra;
            asm("mapa.shared::cluster.u32 %0, %1, %2;" : "=r"(ra) : "r"(la), "r"(0));
            asm volatile("st.shared::cluster.v4.b32 [%0], {%1,%2,%3,%4};"
                :: "r"(ra),
                   "r"(__float_as_uint(csum.x)), "r"(__float_as_uint(csum.y)),
                   "r"(__float_as_uint(csum.z)), "r"(__float_as_uint(csum.w))
                : "memory");
        }
    }
    // cluster barrier 1: rank1's partials visible to rank0
    asm volatile("barrier.cluster.arrive.aligned;" ::: "memory");
    asm volatile("barrier.cluster.wait.aligned;" ::: "memory");

    // ---------- Phase 2: rank0 part0 computes the scan ----------
    if (rank == 0 && part == 0) {
        float4 o4 = peerSum[col];
        const float inv = 1.0f / (float)S_DIM;
        const float x0 = (csum.x + o4.x) * inv;
        const float x1 = (csum.y + o4.y) * inv;
        const float x2 = (csum.z + o4.z) * inv;
        const float x3 = (csum.w + o4.w) * inv;

        // per-thread composite over 4 time steps: state' = m*state + a
        float a = omb * x0;
        a = beta * a + omb * x1;
        a = beta * a + omb * x2;
        a = beta * a + omb * x3;
        float m = beta * beta;
        m = m * m;                    // beta^4

        #pragma unroll
        for (int d = 1; d < 32; d <<= 1) {
            float ap = __shfl_up_sync(0xffffffffu, a, d);
            float mp = __shfl_up_sync(0xffffffffu, m, d);
            if (lane >= d) { a += m * ap; m *= mp; }
        }
        if (lane == 31) { Ms[wid] = m; As[wid] = a; }
        asm volatile("bar.sync 1, 256;" ::: "memory");  // 8 scan warps only

        float pref = 0.0f;
        #pragma unroll
        for (int w = 0; w < 8; ++w) {
            if (w == wid) break;
            pref = Ms[w] * pref + As[w];
        }
        const float a_full = a + m * pref;
        const float a_prev = __shfl_up_sync(0xffffffffu, a_full, 1);
        const float a_excl = (lane > 0) ? a_prev : pref;

        float st = a_excl;
        st = beta * st + omb * x0; const float r0 = st;
        st = beta * st + omb * x1; const float r1 = st;
        st = beta * st + omb * x2; const float r2 = st;
        st = beta * st + omb * x3; const float r3 = st;

        statS[col] = make_float4(r0, r1, r2, r3);
        // DSMEM write of stat into rank1's statS[col]
        uint32_t la = smem_u32(&statS[col]);
        uint32_t ra;
        asm("mapa.shared::cluster.u32 %0, %1, %2;" : "=r"(ra) : "r"(la), "r"(1));
        asm volatile("st.shared::cluster.v4.b32 [%0], {%1,%2,%3,%4};"
            :: "r"(ra),
               "r"(__float_as_uint(r0)), "r"(__float_as_uint(r1)),
               "r"(__float_as_uint(r2)), "r"(__float_as_uint(r3))
            : "memory");
    }
    // cluster barrier 2: stat visible in both CTAs
    asm volatile("barrier.cluster.arrive.aligned;" ::: "memory");
    asm volatile("barrier.cluster.wait.aligned;" ::: "memory");

    // ---------- Phase 3: out = (1-spike)*stat ; re-read hits L2 ----------
    const float4 st4 = statS[col];
    const float4* pr = sp + base + (size_t)srow0 * T4 + col;
    float4* pw = out + base + (size_t)srow0 * T4 + col;
    #pragma unroll
    for (int k = 0; k < ROWS_PER_THREAD; ++k) {
        float4 v = __ldcs(&pr[(size_t)k * T4]);   // last use: evict-first
        float4 o;
        o.x = (1.0f - v.x) * st4.x;
        o.y = (1.0f - v.y) * st4.y;
        o.z = (1.0f - v.z) * st4.z;
        o.w = (1.0f - v.w) * st4.w;
        __stcs(&pw[(size_t)k * T4], o);           // streaming store
    }
}

extern "C" void kernel_launch(void* const* d_in, const int* in_sizes, int n_in,
                              void* d_out, int out_size) {
    const float* spikes = (const float*)d_in[0];
    const float* beta   = (const float*)d_in[1];
    float* out          = (float*)d_out;

    const int nbc = in_sizes[0] / (S_DIM * T_DIM);  // 2048 tiles

    // one cluster (2 CTAs) per tile
    sdb_kernel<<<nbc * 2, THREADS>>>(
        (const float4*)spikes, beta, (float4*)out);
}

// round 7
// speedup vs baseline: 1.4005x; 1.0262x over previous
#include <cuda_runtime.h>
#include <cstdint>

// SignalDualBackground: out[b,c,s,t] = (1 - spikes[b,c,s,t]) * stat[b,c,t]
//   x[b,c,t]  = mean_s spikes[b,c,s,t]            (S=64)
//   stat[.,t] = beta*stat[.,t-1] + (1-beta)*x[.,t], stat[.,-1]=0  (T=1024)
//
// R7: cluster-of-2 shared tile (R6's ideal 1.02GB traffic) with the sync
// bubbles halved: SYMMETRIC partial exchange + REDUNDANT scan. Each rank
// DSMEM-writes its 32-row column sums to the peer, ONE cluster barrier,
// then BOTH ranks compute the same scan locally in parallel (scan warps
// were idle capacity; redundancy costs nothing). No second cluster
// barrier, no rank1-idles-through-scan bubble.

#define T_DIM 1024
#define S_DIM 64
#define THREADS 1024
#define T4 (T_DIM / 4)              // 256 float4 per row
#define ROWS_PER_CTA 32
#define ROWS_PER_THREAD 8           // 32 rows / 4 parts
#define TILE_F4 (S_DIM * T4)        // 16384 float4 per tile

__device__ __forceinline__ uint32_t smem_u32(const void* p) {
    uint32_t a;
    asm("{ .reg .u64 t; cvta.to.shared.u64 t, %1; cvt.u32.u64 %0, t; }"
        : "=r"(a) : "l"(p));
    return a;
}

__global__ __launch_bounds__(THREADS, 2) __cluster_dims__(2, 1, 1)
void sdb_kernel(const float4* __restrict__ sp,
                const float* __restrict__ beta_p,
                float4* __restrict__ out) {
    __shared__ float4 red[THREADS];   // 16KB: per-thread partials
    __shared__ float4 statS[T4];      // 4KB: broadcast stat
    __shared__ float4 peerSum[T4];    // 4KB: peer's 32-row column sums
    __shared__ float Ms[8], As[8];

    const int tid  = threadIdx.x;
    const int col  = tid & (T4 - 1);  // 0..255 time chunk
    const int part = tid >> 8;        // 0..3
    const int lane = tid & 31;
    const int wid  = tid >> 5;        // part0 -> 0..7

    const int rank = (int)(blockIdx.x & 1);      // ctarank within cluster
    const int peer = rank ^ 1;
    const size_t base = (size_t)(blockIdx.x >> 1) * TILE_F4;
    const int srow0 = rank * ROWS_PER_CTA + part * ROWS_PER_THREAD;

    const float beta = beta_p[0];
    const float omb  = 1.0f - beta;

    // ---------- Phase 1: partial sums over this CTA's 8 rows/thread ----------
    const float4* p = sp + base + (size_t)srow0 * T4 + col;
    float4 acc0 = make_float4(0.f, 0.f, 0.f, 0.f);
    float4 acc1 = make_float4(0.f, 0.f, 0.f, 0.f);
    #pragma unroll
    for (int k = 0; k < ROWS_PER_THREAD; k += 2) {
        float4 v0 = p[(size_t)k * T4];
        float4 v1 = p[(size_t)(k + 1) * T4];
        acc0.x += v0.x; acc0.y += v0.y; acc0.z += v0.z; acc0.w += v0.w;
        acc1.x += v1.x; acc1.y += v1.y; acc1.z += v1.z; acc1.w += v1.w;
    }
    acc0.x += acc1.x; acc0.y += acc1.y; acc0.z += acc1.z; acc0.w += acc1.w;
    red[tid] = acc0;
    __syncthreads();

    // per-col sum over this CTA's 32 rows (part 0 only), kept in regs,
    // and symmetric DSMEM push to the peer's peerSum[col]
    float4 csum;
    if (part == 0) {
        float4 a4 = red[col];
        float4 b4 = red[col + 256];
        float4 c4 = red[col + 512];
        float4 d4 = red[col + 768];
        csum.x = a4.x + b4.x + c4.x + d4.x;
        csum.y = a4.y + b4.y + c4.y + d4.y;
        csum.z = a4.z + b4.z + c4.z + d4.z;
        csum.w = a4.w + b4.w + c4.w + d4.w;

        uint32_t la = smem_u32(&peerSum[col]);
        uint32_t ra;
        asm("mapa.shared::cluster.u32 %0, %1, %2;" : "=r"(ra) : "r"(la), "r"(peer));
        asm volatile("st.shared::cluster.v4.b32 [%0], {%1,%2,%3,%4};"
            :: "r"(ra),
               "r"(__float_as_uint(csum.x)), "r"(__float_as_uint(csum.y)),
               "r"(__float_as_uint(csum.z)), "r"(__float_as_uint(csum.w))
            : "memory");
    }
    // single cluster barrier: peer partials visible on both sides
    asm volatile("barrier.cluster.arrive.aligned;" ::: "memory");
    asm volatile("barrier.cluster.wait.aligned;" ::: "memory");

    // ---------- Phase 2: BOTH ranks compute the scan (redundant, parallel) ----------
    if (part == 0) {
        float4 o4 = peerSum[col];
        const float inv = 1.0f / (float)S_DIM;
        const float x0 = (csum.x + o4.x) * inv;
        const float x1 = (csum.y + o4.y) * inv;
        const float x2 = (csum.z + o4.z) * inv;
        const float x3 = (csum.w + o4.w) * inv;

        // per-thread composite over 4 time steps: state' = m*state + a
        float a = omb * x0;
        a = beta * a + omb * x1;
        a = beta * a + omb * x2;
        a = beta * a + omb * x3;
        float m = beta * beta;
        m = m * m;                    // beta^4

        #pragma unroll
        for (int d = 1; d < 32; d <<= 1) {
            float ap = __shfl_up_sync(0xffffffffu, a, d);
            float mp = __shfl_up_sync(0xffffffffu, m, d);
            if (lane >= d) { a += m * ap; m *= mp; }
        }
        if (lane == 31) { Ms[wid] = m; As[wid] = a; }
        asm volatile("bar.sync 1, 256;" ::: "memory");  // 8 scan warps only

        float pref = 0.0f;
        #pragma unroll
        for (int w = 0; w < 8; ++w) {
            if (w == wid) break;
            pref = Ms[w] * pref + As[w];
        }
        const float a_full = a + m * pref;
        const float a_prev = __shfl_up_sync(0xffffffffu, a_full, 1);
        const float a_excl = (lane > 0) ? a_prev : pref;

        float st = a_excl;
        st = beta * st + omb * x0; const float r0 = st;
        st = beta * st + omb * x1; const float r1 = st;
        st = beta * st + omb * x2; const float r2 = st;
        st = beta * st + omb * x3; const float r3 = st;
        statS[col] = make_float4(r0, r1, r2, r3);
    }
    __syncthreads();                  // local stat visible to all warps

    // ---------- Phase 3: out = (1-spike)*stat ; re-read hits L2 ----------
    const float4 st4 = statS[col];
    const float4* pr = sp + base + (size_t)srow0 * T4 + col;
    float4* pw = out + base + (size_t)srow0 * T4 + col;
    #pragma unroll
    for (int k = 0; k < ROWS_PER_THREAD; ++k) {
        float4 v = __ldcs(&pr[(size_t)k * T4]);   // last use: evict-first
        float4 o;
        o.x = (1.0f - v.x) * st4.x;
        o.y = (1.0f - v.y) * st4.y;
        o.z = (1.0f - v.z) * st4.z;
        o.w = (1.0f - v.w) * st4.w;
        __stcs(&pw[(size_t)k * T4], o);           // streaming store
    }
}

extern "C" void kernel_launch(void* const* d_in, const int* in_sizes, int n_in,
                              void* d_out, int out_size) {
    const float* spikes = (const float*)d_in[0];
    const float* beta   = (const float*)d_in[1];
    float* out          = (float*)d_out;

    const int nbc = in_sizes[0] / (S_DIM * T_DIM);  // 2048 tiles

    // one cluster (2 CTAs) per tile
    sdb_kernel<<<nbc * 2, THREADS>>>(
        (const float4*)spikes, beta, (float4*)out);
}